// round 16
// baseline (speedup 1.0000x reference)
#include <cuda_runtime.h>
#include <cuda_bf16.h>

#define JT    128   // j-tile width
#define IT    256   // i-tile height (2 rows per thread)
#define NTHR  128
#define NCTA_MAX 592               // 4 CTAs/SM * 148 SMs
#define MAXB  4096
#define GRPSH 5
#define MAXG  ((MAXB >> GRPSH) + 1)

__device__ double        g_partials[MAXB];
__device__ unsigned int  g_gtick[MAXG];
__device__ unsigned int  g_ticket = 0;
__device__ unsigned int  g_work   = 0;

// Counting step: c = 1.0/0.0 (pred-as-data); cnt += c; w += cnt. Exact ints in fp32.
__device__ __forceinline__ void cstep(float& cnt, float& w, float pi, float pj) {
    float c;
    asm("set.ge.f32.f32 %0, %1, %2;" : "=f"(c) : "f"(pi), "f"(pj));
    cnt += c;
    w   += cnt;
}

// Band step (exact when d <= 10*Delta): val = max(2D*[d>=0] - d, 0).
__device__ __forceinline__ void bstep(float& acc, float& twoD, float pi, float pj) {
    float c;
    asm("set.ge.f32.f32 %0, %1, %2;" : "=f"(c) : "f"(pi), "f"(pj));
    float nd = pj - pi;
    float m  = fmaf(c, twoD, nd);
    acc += fmaxf(m, 0.0f);
    twoD += 8.0f;
}

// Universal sub-diagonal step (exact for ANY d, step==10).
__device__ __forceinline__ void ustep(float& acc, float& twoD, float& eightD,
                                      float pi, float pj) {
    float c;
    asm("set.ge.f32.f32 %0, %1, %2;" : "=f"(c) : "f"(pi), "f"(pj));
    float nd = pj - pi;
    float m  = fmaf(c, twoD, nd);
    float t  = fmaf(m, -1.0f, -eightD);
    acc += fmaxf(m, fmaxf(t, 0.0f));
    twoD   += 8.0f;
    eightD += 32.0f;
}

// Legacy exact scalar row (diagonal/partial tiles, any step).
__device__ __forceinline__ float scal_row(const float* fx, const float* qz,
                                          float pi, float gif, float c02, float step,
                                          int jend) {
    const float P1 = c02 * gif - pi, P2 = pi - step * gif;
    float a = 0.f;
    for (int jj = 0; jj <= jend; ++jj) {
        float t1 = P1 + fx[2 * jj];
        float t2 = P2 + fx[2 * jj + 1];
        float u  = qz[jj] - pi;
        float mm = fmaxf(t1, t2);
        float s  = (u > 0.0f) ? u : mm;
        a += fmaxf(s, 0.0f);
    }
    return a;
}

__global__ void __launch_bounds__(NTHR, 8)
dl_fused_kernel(const float* __restrict__ p,
                const float* __restrict__ z_spacing,
                const float* __restrict__ nth_slice,
                float* __restrict__ out,
                int n, int ntiles, int ncta) {
    __shared__ __align__(16) float sI[IT];
    __shared__ __align__(16) float fxj[2 * JT];
    __shared__ __align__(8)  float qzf[JT];
    __shared__ float  r_max[NTHR / 32], r_min[NTHR / 32];
    __shared__ double wsum[NTHR / 32];
    __shared__ int    s_tile;
    __shared__ bool   is_last;

    const int tid = threadIdx.x;

    const float step = z_spacing[0] * nth_slice[0];   // == 10 exactly for this data
    const float c02  = 0.2f * step;

    double vacc = 0.0;   // per-thread accumulator across all tiles this CTA processes

    // ---- Persistent tile loop (dynamic stealing) ----
    for (;;) {
        if (tid == 0) s_tile = (int)atomicAdd(&g_work, 1u);
        __syncthreads();            // also separates prev tile's reads from new writes
        const int grab = s_tile;
        if (grab >= ntiles) break;

        // Heavy-first: earliest grabs get the diagonal (most expensive) tiles.
        int t  = (ntiles - 1) - grab;
        int ti = (int)((sqrtf(4.0f * (float)t + 1.0f) - 1.0f) * 0.5f);
        while ((ti + 1) * (ti + 2) <= t) ti++;
        while (ti * (ti + 1) > t) ti--;
        const int tj = t - ti * (ti + 1);

        const int gj0  = tj * JT;
        const int base = ti * IT;
        const int jg   = gj0 + tid;

        // Stage j-tile (lane owns one j; pj stays in register).
        float pjreg = (jg < n) ? p[jg] : 0.0f;
        {
            float jf = (float)jg;
            fxj[2 * tid]     = pjreg - c02 * jf;
            fxj[2 * tid + 1] = step * jf - pjreg;
            qzf[tid]         = pjreg;
        }

        const int  gi0 = base + tid, gi1 = gi0 + NTHR;
        const bool v0 = (gi0 < n), v1 = (gi1 < n);
        const float pi0 = v0 ? p[gi0] : 0.0f;
        const float pi1 = v1 ? p[gi1] : 0.0f;
        sI[tid]        = pi0;
        sI[tid + NTHR] = pi1;

        // Classification: pImax (i-tile), pJmin (j-tile).
        {
            float lmax = fmaxf(pi0, pi1);
            float lmin = pjreg;
            #pragma unroll
            for (int off = 16; off > 0; off >>= 1) {
                lmax = fmaxf(lmax, __shfl_xor_sync(0xffffffffu, lmax, off));
                lmin = fminf(lmin, __shfl_xor_sync(0xffffffffu, lmin, off));
            }
            if ((tid & 31) == 0) { r_max[tid >> 5] = lmax; r_min[tid >> 5] = lmin; }
        }
        __syncthreads();

        const float pImax = fmaxf(fmaxf(r_max[0], r_max[1]), fmaxf(r_max[2], r_max[3]));
        const float pJmin = fminf(fminf(r_min[0], r_min[1]), fminf(r_min[2], r_min[3]));
        const float range = pImax - pJmin;

        const int  dminI = base - (gj0 + JT - 1);
        const bool fullt = (base + IT <= n) && (gj0 + JT <= n) && (dminI >= 1) &&
                           (step == 10.0f);

        double v;
        const float4* sI4 = (const float4*)sI;

        if (fullt && range < (float)(2 * dminI)) {
            // Counting: loss = 2*(i-j)*[pi>=pj] - (pi - pj) exactly.
            float c0 = 0.f, w0 = 0.f, c1 = 0.f, w1 = 0.f;
            float c2 = 0.f, w2 = 0.f, c3 = 0.f, w3 = 0.f;
            #pragma unroll 16
            for (int k = 0; k < IT / 4; ++k) {
                float4 q = sI4[k];
                cstep(c0, w0, q.x, pjreg);
                cstep(c1, w1, q.y, pjreg);
                cstep(c2, w2, q.z, pjreg);
                cstep(c3, w3, q.w, pjreg);
            }
            const float CNT = (c0 + c1) + (c2 + c3);
            const float SM  = 4.0f * ((float)(IT / 4) * CNT - ((w0 + w1) + (w2 + w3)))
                            + (c1 + 2.0f * c2 + 3.0f * c3);
            const float tpart = (float)(base - jg) * CNT + SM;
            v = 2.0 * (double)tpart
              - (double)JT * ((double)pi0 + (double)pi1)
              + (double)IT * (double)pjreg;
        } else if (fullt && range <= (float)(10 * dminI)) {
            // Band: loss = max(2D*[d>=0] - d, 0) exactly.
            float d0 = 2.0f * (float)(base - jg);
            float t0 = d0, t1 = d0 + 2.f, t2 = d0 + 4.f, t3 = d0 + 6.f;
            float a0 = 0.f, a1 = 0.f, a2 = 0.f, a3 = 0.f;
            #pragma unroll 16
            for (int k = 0; k < IT / 4; ++k) {
                float4 q = sI4[k];
                bstep(a0, t0, q.x, pjreg);
                bstep(a1, t1, q.y, pjreg);
                bstep(a2, t2, q.z, pjreg);
                bstep(a3, t3, q.w, pjreg);
            }
            v = (double)((a0 + a1) + (a2 + a3));
        } else if (fullt) {
            // Universal sub-diagonal (any d): exact reference semantics.
            float d0 = 2.0f * (float)(base - jg);
            float t0 = d0, t1 = d0 + 2.f, t2 = d0 + 4.f, t3 = d0 + 6.f;
            float e0 = 4.f * t0, e1 = 4.f * t1, e2 = 4.f * t2, e3 = 4.f * t3;
            float a0 = 0.f, a1 = 0.f, a2 = 0.f, a3 = 0.f;
            #pragma unroll 8
            for (int k = 0; k < IT / 4; ++k) {
                float4 q = sI4[k];
                ustep(a0, t0, e0, q.x, pjreg);
                ustep(a1, t1, e1, q.y, pjreg);
                ustep(a2, t2, e2, q.z, pjreg);
                ustep(a3, t3, e3, q.w, pjreg);
            }
            v = (double)((a0 + a1) + (a2 + a3));
        } else {
            // Diagonal / partial tiles: per-row scalar.
            const bool fullj = (gj0 + JT <= n);
            const int  jlim  = fullj ? JT : max(0, n - gj0);
            float acc = 0.f;
            const int rel0 = v0 ? (gi0 - gj0) : -1;
            const int rel1 = v1 ? (gi1 - gj0) : -1;
            if (rel0 >= 0 && jlim > 0)
                acc += scal_row(fxj, qzf, pi0, (float)gi0, c02, step,
                                min(rel0, jlim - 1));
            if (rel1 >= 0 && jlim > 0)
                acc += scal_row(fxj, qzf, pi1, (float)gi1, c02, step,
                                min(rel1, jlim - 1));
            v = (double)acc;
        }

        vacc += v;
        __syncthreads();   // tile fully consumed before next staging overwrites shared
    }

    // ---- Once per CTA: block reduction + completion protocol ----
    double v = vacc;
    #pragma unroll
    for (int off = 16; off > 0; off >>= 1)
        v += __shfl_down_sync(0xffffffffu, v, off);
    if ((tid & 31) == 0) wsum[tid >> 5] = v;
    __syncthreads();
    if (tid < 32) {
        v = (tid < (NTHR / 32)) ? wsum[tid] : 0.0;
        #pragma unroll
        for (int off = 2; off > 0; off >>= 1)
            v += __shfl_down_sync(0xffffffffu, v, off);
        if (tid == 0) {
            g_partials[blockIdx.x] = v;
            __threadfence();
            const int grp     = (int)blockIdx.x >> GRPSH;
            const int ngroups = (ncta + (1 << GRPSH) - 1) >> GRPSH;
            const int gcnt    = min(1 << GRPSH, ncta - (grp << GRPSH));
            bool last = false;
            unsigned g1 = atomicAdd(&g_gtick[grp], 1u);
            if (g1 == (unsigned)(gcnt - 1)) {
                g_gtick[grp] = 0;
                __threadfence();
                unsigned g2 = atomicAdd(&g_ticket, 1u);
                last = (g2 == (unsigned)(ngroups - 1));
            }
            is_last = last;
        }
    }
    __syncthreads();

    if (is_last) {
        __threadfence();
        double s = 0.0;
        for (int i = tid; i < ncta; i += NTHR)
            s += g_partials[i];
        #pragma unroll
        for (int off = 16; off > 0; off >>= 1)
            s += __shfl_down_sync(0xffffffffu, s, off);
        if ((tid & 31) == 0) wsum[tid >> 5] = s;
        __syncthreads();
        if (tid == 0) {
            double tot = 0.0;
            #pragma unroll
            for (int w = 0; w < NTHR / 32; ++w) tot += wsum[w];
            double nn = (double)n * (double)n;
            out[0] = (float)(tot / nn);
            g_ticket = 0;
            g_work   = 0;   // reset work counter for next graph replay
        }
    }
}

extern "C" void kernel_launch(void* const* d_in, const int* in_sizes, int n_in,
                              void* d_out, int out_size) {
    const float* p   = (const float*)d_in[0];
    const float* z   = (const float*)d_in[1];
    const float* nth = (const float*)d_in[2];
    float* out = (float*)d_out;
    int n = in_sizes[0];

    int nti    = (n + IT - 1) / IT;
    int ntiles = nti * (nti + 1);          // n = 8192 -> 1056
    int ncta   = ntiles < NCTA_MAX ? ntiles : NCTA_MAX;
    if (ncta > MAXB) ncta = MAXB;

    dl_fused_kernel<<<ncta, NTHR>>>(p, z, nth, out, n, ntiles, ncta);
}

// round 17
// speedup vs baseline: 1.0802x; 1.0802x over previous
#include <cuda_runtime.h>
#include <cuda_bf16.h>

#define JT    128   // j-tile width
#define IT    128   // i-tile height (1 row per thread)
#define NTHR  128
#define MAXB  4096
#define GRPSH 5
#define MAXG  ((MAXB >> GRPSH) + 1)

__device__ double        g_partials[MAXB];
__device__ unsigned int  g_gtick[MAXG];
__device__ unsigned int  g_ticket = 0;

// Counting step: c = 1.0/0.0 (pred-as-data); cnt += c; w += cnt. Exact ints in fp32.
__device__ __forceinline__ void cstep(float& cnt, float& w, float pi, float pj) {
    float c;
    asm("set.ge.f32.f32 %0, %1, %2;" : "=f"(c) : "f"(pi), "f"(pj));
    cnt += c;
    w   += cnt;
}

// Band step (exact when d <= 10*Delta): val = max(2D*[d>=0] - d, 0).
__device__ __forceinline__ void bstep(float& acc, float& twoD, float pi, float pj) {
    float c;
    asm("set.ge.f32.f32 %0, %1, %2;" : "=f"(c) : "f"(pi), "f"(pj));
    float nd = pj - pi;
    float m  = fmaf(c, twoD, nd);
    acc += fmaxf(m, 0.0f);
    twoD += 8.0f;
}

// Universal sub-diagonal step (exact for ANY d, step==10):
// val = max(m, max(fl(-m - 8D), 0)), m = fl(2D*[d>=0] - d).
__device__ __forceinline__ void ustep(float& acc, float& twoD, float& eightD,
                                      float pi, float pj) {
    float c;
    asm("set.ge.f32.f32 %0, %1, %2;" : "=f"(c) : "f"(pi), "f"(pj));
    float nd = pj - pi;
    float m  = fmaf(c, twoD, nd);
    float t  = fmaf(m, -1.0f, -eightD);
    acc += fmaxf(m, fmaxf(t, 0.0f));
    twoD   += 8.0f;
    eightD += 32.0f;
}

// Legacy exact scalar row (diagonal/partial tiles, any step).
__device__ __forceinline__ float scal_row(const float* fx, const float* qz,
                                          float pi, float gif, float c02, float step,
                                          int jend) {
    const float P1 = c02 * gif - pi, P2 = pi - step * gif;
    float a = 0.f;
    for (int jj = 0; jj <= jend; ++jj) {
        float t1 = P1 + fx[2 * jj];
        float t2 = P2 + fx[2 * jj + 1];
        float u  = qz[jj] - pi;
        float mm = fmaxf(t1, t2);
        float s  = (u > 0.0f) ? u : mm;
        a += fmaxf(s, 0.0f);
    }
    return a;
}

__global__ void __launch_bounds__(NTHR, 12)
dl_fused_kernel(const float* __restrict__ p,
                const float* __restrict__ z_spacing,
                const float* __restrict__ nth_slice,
                float* __restrict__ out,
                int n, int nblocks) {
    __shared__ __align__(16) float sI[IT];
    __shared__ __align__(16) float fxj[2 * JT];
    __shared__ __align__(8)  float qzf[JT];
    __shared__ float  r_max[NTHR / 32], r_min[NTHR / 32];
    __shared__ double wsum[NTHR / 32];
    __shared__ bool   is_last;

    const int tid = threadIdx.x;

    // Heavy-first: highest t (diagonal) gets lowest blockIdx.
    int t  = (nblocks - 1) - blockIdx.x;
    // Decode lower-triangular (ti, tj): per-ti count = ti + 1, start = ti*(ti+1)/2.
    int ti = (int)((sqrtf(8.0f * (float)t + 1.0f) - 1.0f) * 0.5f);
    while ((ti + 1) * (ti + 2) / 2 <= t) ti++;
    while (ti * (ti + 1) / 2 > t) ti--;
    const int tj = t - ti * (ti + 1) / 2;

    const float step = z_spacing[0] * nth_slice[0];   // == 10 exactly for this data
    const float c02  = 0.2f * step;

    const int gj0  = tj * JT;
    const int base = ti * IT;
    const int jg   = gj0 + tid;

    // Stage j-tile (lane owns one j; pj stays in register).
    float pjreg;
    {
        pjreg = (jg < n) ? p[jg] : 0.0f;
        float jf = (float)jg;
        fxj[2 * tid]     = pjreg - c02 * jf;
        fxj[2 * tid + 1] = step * jf - pjreg;
        qzf[tid]         = pjreg;
    }

    const int  gi0 = base + tid;
    const bool v0  = (gi0 < n);
    const float pi0 = v0 ? p[gi0] : 0.0f;
    sI[tid] = pi0;

    // Classification: pImax (i-tile), pJmin (j-tile).
    {
        float lmax = pi0;
        float lmin = pjreg;
        #pragma unroll
        for (int off = 16; off > 0; off >>= 1) {
            lmax = fmaxf(lmax, __shfl_xor_sync(0xffffffffu, lmax, off));
            lmin = fminf(lmin, __shfl_xor_sync(0xffffffffu, lmin, off));
        }
        if ((tid & 31) == 0) { r_max[tid >> 5] = lmax; r_min[tid >> 5] = lmin; }
    }
    __syncthreads();

    const float pImax = fmaxf(fmaxf(r_max[0], r_max[1]), fmaxf(r_max[2], r_max[3]));
    const float pJmin = fminf(fminf(r_min[0], r_min[1]), fminf(r_min[2], r_min[3]));
    const float range = pImax - pJmin;

    const int  dminI = base - (gj0 + JT - 1);
    const bool fullt = (base + IT <= n) && (gj0 + JT <= n) && (dminI >= 1) &&
                       (step == 10.0f);

    double v;
    const float4* sI4 = (const float4*)sI;

    if (fullt && range < (float)(2 * dminI)) {
        // Counting: loss = 2*(i-j)*[pi>=pj] - (pi - pj) exactly (d < 2D everywhere).
        float c0 = 0.f, w0 = 0.f, c1 = 0.f, w1 = 0.f;
        float c2 = 0.f, w2 = 0.f, c3 = 0.f, w3 = 0.f;
        #pragma unroll 16
        for (int k = 0; k < IT / 4; ++k) {
            float4 q = sI4[k];
            cstep(c0, w0, q.x, pjreg);
            cstep(c1, w1, q.y, pjreg);
            cstep(c2, w2, q.z, pjreg);
            cstep(c3, w3, q.w, pjreg);
        }
        const float CNT = (c0 + c1) + (c2 + c3);
        const float SM  = 4.0f * ((float)(IT / 4) * CNT - ((w0 + w1) + (w2 + w3)))
                        + (c1 + 2.0f * c2 + 3.0f * c3);
        const float tpart = (float)(base - jg) * CNT + SM;   // Sum_i (i-j)*[pi>=pj]
        v = 2.0 * (double)tpart
          - (double)JT * (double)pi0
          + (double)IT * (double)pjreg;
    } else if (fullt && range <= (float)(10 * dminI)) {
        // Band: loss = max(2D*[d>=0] - d, 0) exactly (d <= 10D everywhere).
        float d0 = 2.0f * (float)(base - jg);
        float t0 = d0, t1 = d0 + 2.f, t2 = d0 + 4.f, t3 = d0 + 6.f;
        float a0 = 0.f, a1 = 0.f, a2 = 0.f, a3 = 0.f;
        #pragma unroll 16
        for (int k = 0; k < IT / 4; ++k) {
            float4 q = sI4[k];
            bstep(a0, t0, q.x, pjreg);
            bstep(a1, t1, q.y, pjreg);
            bstep(a2, t2, q.z, pjreg);
            bstep(a3, t3, q.w, pjreg);
        }
        v = (double)((a0 + a1) + (a2 + a3));
    } else if (fullt) {
        // Universal sub-diagonal (any d): exact reference semantics.
        float d0 = 2.0f * (float)(base - jg);
        float t0 = d0, t1 = d0 + 2.f, t2 = d0 + 4.f, t3 = d0 + 6.f;
        float e0 = 4.f * t0, e1 = 4.f * t1, e2 = 4.f * t2, e3 = 4.f * t3;
        float a0 = 0.f, a1 = 0.f, a2 = 0.f, a3 = 0.f;
        #pragma unroll 8
        for (int k = 0; k < IT / 4; ++k) {
            float4 q = sI4[k];
            ustep(a0, t0, e0, q.x, pjreg);
            ustep(a1, t1, e1, q.y, pjreg);
            ustep(a2, t2, e2, q.z, pjreg);
            ustep(a3, t3, e3, q.w, pjreg);
        }
        v = (double)((a0 + a1) + (a2 + a3));
    } else {
        // Diagonal / partial tiles: per-row scalar.
        const bool fullj = (gj0 + JT <= n);
        const int  jlim  = fullj ? JT : max(0, n - gj0);
        float acc = 0.f;
        const int rel0 = v0 ? (gi0 - gj0) : -1;
        if (rel0 >= 0 && jlim > 0)
            acc += scal_row(fxj, qzf, pi0, (float)gi0, c02, step,
                            min(rel0, jlim - 1));
        v = (double)acc;
    }

    // Block reduction in double.
    #pragma unroll
    for (int off = 16; off > 0; off >>= 1)
        v += __shfl_down_sync(0xffffffffu, v, off);
    if ((tid & 31) == 0) wsum[tid >> 5] = v;
    __syncthreads();
    if (tid < 32) {
        v = (tid < (NTHR / 32)) ? wsum[tid] : 0.0;
        #pragma unroll
        for (int off = 2; off > 0; off >>= 1)
            v += __shfl_down_sync(0xffffffffu, v, off);
        if (tid == 0) {
            g_partials[blockIdx.x] = v;
            __threadfence();
            // Two-level completion (<=32 contenders per address).
            const int grp     = (int)blockIdx.x >> GRPSH;
            const int ngroups = (nblocks + (1 << GRPSH) - 1) >> GRPSH;
            const int gcnt    = min(1 << GRPSH, nblocks - (grp << GRPSH));
            bool last = false;
            unsigned g1 = atomicAdd(&g_gtick[grp], 1u);
            if (g1 == (unsigned)(gcnt - 1)) {
                g_gtick[grp] = 0;   // reset for next graph replay
                __threadfence();
                unsigned g2 = atomicAdd(&g_ticket, 1u);
                last = (g2 == (unsigned)(ngroups - 1));
            }
            is_last = last;
        }
    }
    __syncthreads();

    // Last block: final reduce, write output, reset ticket.
    if (is_last) {
        __threadfence();
        double s = 0.0;
        for (int i = tid; i < nblocks; i += NTHR)
            s += g_partials[i];
        #pragma unroll
        for (int off = 16; off > 0; off >>= 1)
            s += __shfl_down_sync(0xffffffffu, s, off);
        if ((tid & 31) == 0) wsum[tid >> 5] = s;
        __syncthreads();
        if (tid == 0) {
            double tot = 0.0;
            #pragma unroll
            for (int w = 0; w < NTHR / 32; ++w) tot += wsum[w];
            double nn = (double)n * (double)n;
            out[0] = (float)(tot / nn);
            g_ticket = 0;   // reset for next graph replay
        }
    }
}

extern "C" void kernel_launch(void* const* d_in, const int* in_sizes, int n_in,
                              void* d_out, int out_size) {
    const float* p   = (const float*)d_in[0];
    const float* z   = (const float*)d_in[1];
    const float* nth = (const float*)d_in[2];
    float* out = (float*)d_out;
    int n = in_sizes[0];

    int nti = (n + IT - 1) / IT;
    int nblocks = nti * (nti + 1) / 2;   // n = 8192 -> 2080
    if (nblocks > MAXB) nblocks = MAXB;

    dl_fused_kernel<<<nblocks, NTHR>>>(p, z, nth, out, n, nblocks);
}